// round 7
// baseline (speedup 1.0000x reference)
#include <cuda_runtime.h>
#include <cuda_bf16.h>
#include <cuda_fp16.h>
#include <cstdint>

// ============================================================================
// out[64,8] = exp(-1e-4 * ||x_b - c_j||^2) @ fc_w.T + fc_b
//   x: [64, 65536] f32, centers: [500, 65536] f32
// K1: split-K x split-M. grid = 256 k-chunks x 2 m-halves = 512 CTAs,
//     256 thr, 65.5KB smem, 3 CTAs/SM. Per CTA: convert x chunk (32KB bf16),
//     then 4 sub-blocks of 64 center rows: convert (front-batched LDG) ->
//     mma.sync bf16 -> f16 partials. Exact fp32 norms fused into conversion.
// K2: reduce partials over S + norms -> rbf[c][b].   K3: fc head.
// Base sm_100 only (harness compiles compute_100: no tcgen05).
// ============================================================================

#define GAMMA_F 1e-4f

static constexpr int S_SPLIT = 256;   // K chunks
static constexpr int KC      = 256;   // K per chunk
static constexpr int NB      = 64;    // batch
static constexpr int NCPAD   = 512;
static constexpr int NSB     = 4;     // 64-row center sub-blocks per CTA (half of M)

// -------- scratch --------
__device__ __half g_parth[(size_t)NCPAD * S_SPLIT * NB];  // [c][s][b] 16 MB f16
__device__ float  g_csq_p[(size_t)NCPAD * S_SPLIT];
__device__ float  g_xsq_p[(size_t)NB    * S_SPLIT];       // [b][s]
__device__ float  g_rbf  [(size_t)NCPAD * NB];            // [c][b]

// -------- helpers --------
__device__ __forceinline__ uint32_t smem_u32(const void* p) {
    uint32_t a;
    asm("{ .reg .u64 t; cvta.to.shared.u64 t, %1; cvt.u32.u64 %0, t; }" : "=r"(a) : "l"(p));
    return a;
}
__device__ __forceinline__ uint32_t sw128(uint32_t off) { return off ^ ((off >> 3) & 0x70); }

// 64-row x 256-k bf16 tile, blocked atoms (8 rows x 64 bf16 = 1024B)
__device__ __forceinline__ uint32_t t64_off(int row, int k) {
    uint32_t b = (((uint32_t)(k >> 6) * 8u + (uint32_t)(row >> 3)) << 10)
               + (uint32_t)(row & 7) * 128u + (uint32_t)(k & 63) * 2u;
    return sw128(b);
}
__device__ __forceinline__ uint32_t pack_bf16x2(float a, float b) {
    __nv_bfloat162 t = __floats2bfloat162_rn(a, b);
    return *reinterpret_cast<uint32_t*>(&t);
}
__device__ __forceinline__ void ldsm_x4(uint32_t* r, uint32_t addr) {
    asm volatile("ldmatrix.sync.aligned.m8n8.x4.shared.b16 {%0,%1,%2,%3}, [%4];"
                 : "=r"(r[0]), "=r"(r[1]), "=r"(r[2]), "=r"(r[3]) : "r"(addr));
}
__device__ __forceinline__ void mma_bf16(float* d, const uint32_t* a, const uint32_t* b) {
    asm volatile("mma.sync.aligned.m16n8k16.row.col.f32.bf16.bf16.f32 "
                 "{%0,%1,%2,%3}, {%4,%5,%6,%7}, {%8,%9}, {%0,%1,%2,%3};"
                 : "+f"(d[0]), "+f"(d[1]), "+f"(d[2]), "+f"(d[3])
                 : "r"(a[0]), "r"(a[1]), "r"(a[2]), "r"(a[3]), "r"(b[0]), "r"(b[1]));
}

// convert one 64-f32 row-segment (16 float4) into swizzled bf16 tile, batched
__device__ __forceinline__ float conv64(const float4* __restrict__ gp, char* sbase, int r7,
                                        bool valid) {
    float acc = 0.f;
    if (valid) {
        #pragma unroll
        for (int h = 0; h < 2; h++) {
            float4 v[8];
            #pragma unroll
            for (int j = 0; j < 8; j++) v[j] = gp[h * 8 + j];      // front-batched LDG.128
            #pragma unroll
            for (int j2 = 0; j2 < 4; j2++) {
                float4 a0 = v[2 * j2], a1 = v[2 * j2 + 1];
                acc += a0.x * a0.x + a0.y * a0.y + a0.z * a0.z + a0.w * a0.w;
                acc += a1.x * a1.x + a1.y * a1.y + a1.z * a1.z + a1.w * a1.w;
                uint4 pk = make_uint4(pack_bf16x2(a0.x, a0.y), pack_bf16x2(a0.z, a0.w),
                                      pack_bf16x2(a1.x, a1.y), pack_bf16x2(a1.z, a1.w));
                *reinterpret_cast<uint4*>(sbase + (((h * 4 + j2) ^ r7) << 4)) = pk;
            }
        }
    } else {
        #pragma unroll
        for (int j = 0; j < 8; j++)
            *reinterpret_cast<uint4*>(sbase + ((j ^ r7) << 4)) = make_uint4(0u, 0u, 0u, 0u);
    }
    return acc;
}

// -------- SMEM layout (dynamic): x 32KB | c 32KB | sq 1KB --------
static constexpr int SMEM_X     = 0;
static constexpr int SMEM_C     = 32768;
static constexpr int SMEM_SQ    = 65536;
static constexpr int SMEM_TOTAL = 65536 + 4 * 64 * 4;   // 66560

// ============================================================================
// Kernel 1
// ============================================================================
__global__ void __launch_bounds__(256, 3)
svm_main_kernel(const float* __restrict__ x, const float* __restrict__ centers) {
    extern __shared__ char smem[];
    const uint32_t smem_base = smem_u32(smem);
    float* sq = reinterpret_cast<float*>(smem + SMEM_SQ);
    const int tid = threadIdx.x;
    const int wid = tid >> 5;
    const int lid = tid & 31;
    const int s   = blockIdx.x >> 1;       // k-chunk
    const int mh  = blockIdx.x & 1;        // m-half (center rows mh*256..)
    const size_t k0 = (size_t)s * KC;

    const int row = tid & 63;
    const int kb  = tid >> 6;              // 0..3 (64-k block)
    const int r7  = row & 7;
    const uint32_t conv_off = ((uint32_t)(kb * 8 + (row >> 3)) << 10) + (uint32_t)r7 * 128u;

    // ---- prologue: convert x chunk ----
    {
        const float4* xp = reinterpret_cast<const float4*>(x + (size_t)row * 65536 + k0 + kb * 64);
        sq[kb * 64 + row] = conv64(xp, smem + SMEM_X + conv_off, r7, true);
    }
    __syncthreads();
    if (mh == 0 && tid < 64) {
        g_xsq_p[(size_t)tid * S_SPLIT + s] =
            sq[tid] + sq[64 + tid] + sq[128 + tid] + sq[192 + tid];
    }

    // ---- MMA lane constants: 8 warps = 2(M:32) x 4(N:16) ----
    const int mr    = (wid & 1) * 32;
    const int nbase = (wid >> 1) * 16;
    const int sel = lid >> 3;
    const int l7  = lid & 7;
    const int a_row = l7 + (sel & 1) * 8;
    const int a_kd  = (sel >> 1) * 8;
    const int b_row = nbase + l7 + (sel >> 1) * 8;
    const int b_kd  = (sel & 1) * 8;
    const uint32_t xb = smem_base + SMEM_X;
    const uint32_t cb = smem_base + SMEM_C;

    for (int sb = 0; sb < NSB; sb++) {
        __syncthreads();   // WAR: prev MMA done reading c tile (also xsq read)

        // ---- convert center sub-block (64 rows) ----
        const int grow = mh * 256 + sb * 64 + row;
        {
            const float4* cp =
                reinterpret_cast<const float4*>(centers + (size_t)grow * 65536 + k0 + kb * 64);
            sq[kb * 64 + row] = conv64(cp, smem + SMEM_C + conv_off, r7, grow < 500);
        }
        __syncthreads();

        if (tid < 64) {
            g_csq_p[(size_t)(mh * 256 + sb * 64 + tid) * S_SPLIT + s] =
                sq[tid] + sq[64 + tid] + sq[128 + tid] + sq[192 + tid];
        }

        // ---- MMA: 32x16 warp tile over KC=256 ----
        float acc[2][2][4];
        #pragma unroll
        for (int mi = 0; mi < 2; mi++)
            #pragma unroll
            for (int g = 0; g < 2; g++)
                #pragma unroll
                for (int i = 0; i < 4; i++) acc[mi][g][i] = 0.f;

        #pragma unroll 8
        for (int kk = 0; kk < KC; kk += 16) {
            uint32_t af0[4], af1[4], bf[4];
            ldsm_x4(af0, cb + t64_off(mr + a_row,      kk + a_kd));
            ldsm_x4(af1, cb + t64_off(mr + 16 + a_row, kk + a_kd));
            ldsm_x4(bf,  xb + t64_off(b_row,           kk + b_kd));
            mma_bf16(acc[0][0], af0, bf);
            mma_bf16(acc[0][1], af0, bf + 2);
            mma_bf16(acc[1][0], af1, bf);
            mma_bf16(acc[1][1], af1, bf + 2);
        }

        // ---- store f16 partials ----
        {
            const int r0 = mh * 256 + sb * 64 + mr + (lid >> 2);
            const int c0 = nbase + (lid & 3) * 2;
            #pragma unroll
            for (int mi = 0; mi < 2; mi++) {
                #pragma unroll
                for (int g = 0; g < 2; g++) {
                    const int col = c0 + 8 * g;
                    __half* b0 = g_parth + (((size_t)(r0 + 16 * mi)     * S_SPLIT + s) << 6) + col;
                    __half* b1 = g_parth + (((size_t)(r0 + 16 * mi + 8) * S_SPLIT + s) << 6) + col;
                    *reinterpret_cast<__half2*>(b0) = __floats2half2_rn(acc[mi][g][0], acc[mi][g][1]);
                    *reinterpret_cast<__half2*>(b1) = __floats2half2_rn(acc[mi][g][2], acc[mi][g][3]);
                }
            }
        }
    }
}

// ============================================================================
// Kernel 2: reduce partials over S + finalize norms -> rbf[c][b]
// ============================================================================
__global__ void __launch_bounds__(512)
svm_rbf_kernel() {
    __shared__ float red [16][NB];
    __shared__ float redx[4][NB];
    __shared__ float s_csq;
    const int c   = blockIdx.x;          // 0..499
    const int tid = threadIdx.x;         // 512
    const int sp   = tid >> 5;           // 0..15 (16 s-values each)
    const int lane = tid & 31;           // b-pair index

    // cross partials: coalesced half2 stream
    {
        const __half2* p =
            reinterpret_cast<const __half2*>(g_parth + ((size_t)c * S_SPLIT + sp * 16) * NB) + lane;
        float2 a = make_float2(0.f, 0.f);
        #pragma unroll
        for (int i = 0; i < 16; i++) {
            float2 f = __half22float2(p[(size_t)i * 32]);
            a.x += f.x; a.y += f.y;
        }
        red[sp][2 * lane]     = a.x;
        red[sp][2 * lane + 1] = a.y;
    }
    // xsq: 4 threads per batch row
    if (tid < 256) {
        const int b = tid >> 2, q = tid & 3;
        const float4* xp = reinterpret_cast<const float4*>(g_xsq_p + (size_t)b * S_SPLIT + q * 64);
        float v = 0.f;
        #pragma unroll
        for (int i = 0; i < 16; i++) {
            float4 t = xp[i];
            v += t.x + t.y + t.z + t.w;
        }
        redx[q][b] = v;
    }
    // csq: warp 0
    if (tid < 32) {
        const float4* cp = reinterpret_cast<const float4*>(g_csq_p + (size_t)c * S_SPLIT);
        float4 t0 = cp[tid], t1 = cp[tid + 32];
        float v = t0.x + t0.y + t0.z + t0.w + t1.x + t1.y + t1.z + t1.w;
        #pragma unroll
        for (int d = 16; d > 0; d >>= 1) v += __shfl_xor_sync(0xffffffffu, v, d);
        if (tid == 0) s_csq = v;
    }
    __syncthreads();
    if (tid < NB) {
        float cross = 0.f, xs = 0.f;
        #pragma unroll
        for (int i = 0; i < 16; i++) cross += red[i][tid];
        #pragma unroll
        for (int i = 0; i < 4; i++) xs += redx[i][tid];
        float dist = xs - 2.0f * cross + s_csq;
        g_rbf[(size_t)c * NB + tid] = expf(-GAMMA_F * dist);
    }
}

// ============================================================================
// Kernel 3: out[b][i] = sum_c rbf[c][b] * fc_w[i][c] + fc_b[i]
// ============================================================================
__global__ void svm_fc_kernel(const float* __restrict__ fc_w,
                              const float* __restrict__ fc_b,
                              float* __restrict__ out) {
    const int b   = blockIdx.x;          // 0..63
    const int i   = threadIdx.x >> 5;    // 0..7 output feature
    const int lid = threadIdx.x & 31;
    float acc = 0.f;
    for (int c = lid; c < 500; c += 32)
        acc += g_rbf[(size_t)c * NB + b] * fc_w[i * 500 + c];
    #pragma unroll
    for (int d = 16; d > 0; d >>= 1) acc += __shfl_xor_sync(0xffffffffu, acc, d);
    if (lid == 0) out[b * 8 + i] = acc + fc_b[i];
}

// ============================================================================
extern "C" void kernel_launch(void* const* d_in, const int* in_sizes, int n_in,
                              void* d_out, int out_size) {
    const float* x       = (const float*)d_in[0];
    const float* centers = (const float*)d_in[1];
    const float* fc_w    = (const float*)d_in[2];
    const float* fc_b    = (const float*)d_in[3];
    float* out = (float*)d_out;

    cudaFuncSetAttribute(svm_main_kernel, cudaFuncAttributeMaxDynamicSharedMemorySize, SMEM_TOTAL);

    svm_main_kernel<<<2 * S_SPLIT, 256, SMEM_TOTAL>>>(x, centers);
    svm_rbf_kernel<<<500, 512>>>();
    svm_fc_kernel<<<NB, 256>>>(fc_w, fc_b, out);
}

// round 9
// speedup vs baseline: 1.6124x; 1.6124x over previous
#include <cuda_runtime.h>
#include <cuda_bf16.h>
#include <cuda_fp16.h>
#include <cstdint>

// ============================================================================
// out[64,8] = exp(-1e-4 * ||x_b - c_j||^2) @ fc_w.T + fc_b
//   x: [64, 65536] f32, centers: [500, 65536] f32
// K1: split-K x split-M (grid 512). COALESCED conversion: warp w converts
//     rows 8w..8w+7; 32 lanes read consecutive float4 of ONE row (4 L1
//     wavefronts per LDG.128 instead of 32). Exact norms via warp reduce.
//     mma.sync bf16 -> f16 partials.
// K2: reduce partials over S + norms -> rbf[b][c].   K3: fc head.
// Base sm_100 only (harness compiles compute_100: no tcgen05).
// ============================================================================

#define GAMMA_F 1e-4f

static constexpr int S_SPLIT = 256;   // K chunks
static constexpr int KC      = 256;   // K per chunk
static constexpr int NB      = 64;    // batch
static constexpr int NCPAD   = 512;
static constexpr int NSB     = 4;     // 64-row center sub-blocks per CTA

// -------- scratch --------
__device__ __half g_parth[(size_t)NCPAD * S_SPLIT * NB];  // [c][s][b] 16 MB f16
__device__ float  g_csq_p[(size_t)NCPAD * S_SPLIT];
__device__ float  g_xsq_p[(size_t)NB    * S_SPLIT];       // [b][s]
__device__ float  g_rbf  [(size_t)NB * NCPAD];            // [b][c]

// -------- helpers --------
__device__ __forceinline__ uint32_t smem_u32(const void* p) {
    uint32_t a;
    asm("{ .reg .u64 t; cvta.to.shared.u64 t, %1; cvt.u32.u64 %0, t; }" : "=r"(a) : "l"(p));
    return a;
}

// 64-row x 256-k bf16 tile, blocked atoms (8 rows x 64 bf16 = 1024B), swizzled
__device__ __forceinline__ uint32_t roff(int row, int k) {
    uint32_t r7 = (uint32_t)(row & 7);
    return (((uint32_t)(k >> 6) * 8u + (uint32_t)(row >> 3)) << 10)
         + r7 * 128u
         + (((uint32_t)(k & 63) * 2u) ^ (r7 << 4));
}
__device__ __forceinline__ uint32_t pack_bf16x2(float a, float b) {
    __nv_bfloat162 t = __floats2bfloat162_rn(a, b);
    return *reinterpret_cast<uint32_t*>(&t);
}
__device__ __forceinline__ void ldsm_x4(uint32_t* r, uint32_t addr) {
    asm volatile("ldmatrix.sync.aligned.m8n8.x4.shared.b16 {%0,%1,%2,%3}, [%4];"
                 : "=r"(r[0]), "=r"(r[1]), "=r"(r[2]), "=r"(r[3]) : "r"(addr));
}
__device__ __forceinline__ void mma_bf16(float* d, const uint32_t* a, const uint32_t* b) {
    asm volatile("mma.sync.aligned.m16n8k16.row.col.f32.bf16.bf16.f32 "
                 "{%0,%1,%2,%3}, {%4,%5,%6,%7}, {%8,%9}, {%0,%1,%2,%3};"
                 : "+f"(d[0]), "+f"(d[1]), "+f"(d[2]), "+f"(d[3])
                 : "r"(a[0]), "r"(a[1]), "r"(a[2]), "r"(a[3]), "r"(b[0]), "r"(b[1]));
}
__device__ __forceinline__ float dot4(float4 v) {
    return v.x * v.x + v.y * v.y + v.z * v.z + v.w * v.w;
}
__device__ __forceinline__ float warp_sum(float v) {
    #pragma unroll
    for (int d = 16; d > 0; d >>= 1) v += __shfl_xor_sync(0xffffffffu, v, d);
    return v;
}

// -------- SMEM layout (dynamic): x 32KB | c 32KB --------
static constexpr int SMEM_X     = 0;
static constexpr int SMEM_C     = 32768;
static constexpr int SMEM_TOTAL = 65536;

// ============================================================================
// Kernel 1
// ============================================================================
__global__ void __launch_bounds__(256, 3)
svm_main_kernel(const float* __restrict__ x, const float* __restrict__ centers) {
    extern __shared__ char smem[];
    const uint32_t smem_base = smem_u32(smem);
    const int tid = threadIdx.x;
    const int wid = tid >> 5;
    const int lid = tid & 31;
    const int s   = blockIdx.x >> 1;       // k-chunk
    const int mh  = blockIdx.x & 1;        // m-half
    const size_t k0 = (size_t)s * KC;

    const int kA = 4 * lid, kB = 128 + 4 * lid;   // per-lane k coords of the row

    // ---- prologue: convert x chunk; warp w -> rows 8w..8w+7, coalesced ----
    {
        char* tile = smem + SMEM_X;
        #pragma unroll
        for (int q = 0; q < 8; q += 2) {
            const int r0 = wid * 8 + q, r1 = r0 + 1;
            const float4* g0 = reinterpret_cast<const float4*>(x + (size_t)r0 * 65536 + k0);
            const float4* g1 = reinterpret_cast<const float4*>(x + (size_t)r1 * 65536 + k0);
            float4 a0 = g0[lid], b0 = g0[lid + 32];       // front-batched, coalesced
            float4 a1 = g1[lid], b1 = g1[lid + 32];
            *reinterpret_cast<uint2*>(tile + roff(r0, kA)) =
                make_uint2(pack_bf16x2(a0.x, a0.y), pack_bf16x2(a0.z, a0.w));
            *reinterpret_cast<uint2*>(tile + roff(r0, kB)) =
                make_uint2(pack_bf16x2(b0.x, b0.y), pack_bf16x2(b0.z, b0.w));
            *reinterpret_cast<uint2*>(tile + roff(r1, kA)) =
                make_uint2(pack_bf16x2(a1.x, a1.y), pack_bf16x2(a1.z, a1.w));
            *reinterpret_cast<uint2*>(tile + roff(r1, kB)) =
                make_uint2(pack_bf16x2(b1.x, b1.y), pack_bf16x2(b1.z, b1.w));
            float s0 = warp_sum(dot4(a0) + dot4(b0));
            float s1 = warp_sum(dot4(a1) + dot4(b1));
            if (mh == 0 && lid == 0) {
                g_xsq_p[(size_t)r0 * S_SPLIT + s] = s0;
                g_xsq_p[(size_t)r1 * S_SPLIT + s] = s1;
            }
        }
    }
    __syncthreads();

    // ---- MMA lane constants: 8 warps = 2(M:32) x 4(N:16) ----
    const int mr    = (wid & 1) * 32;
    const int nbase = (wid >> 1) * 16;
    const int sel = lid >> 3;
    const int l7  = lid & 7;
    const int a_row = l7 + (sel & 1) * 8;
    const int a_kd  = (sel >> 1) * 8;
    const int b_row = nbase + l7 + (sel >> 1) * 8;
    const int b_kd  = (sel & 1) * 8;
    const uint32_t xb = smem_base + SMEM_X;
    const uint32_t cb = smem_base + SMEM_C;

    for (int sb = 0; sb < NSB; sb++) {
        __syncthreads();   // WAR: prev MMA done reading c tile

        // ---- convert center sub-block (warp w -> rows 8w..8w+7) ----
        {
            char* tile = smem + SMEM_C;
            const int gbase = mh * 256 + sb * 64;
            #pragma unroll
            for (int q = 0; q < 8; q += 2) {
                const int r0 = wid * 8 + q, r1 = r0 + 1;
                const int gr0 = gbase + r0, gr1 = gbase + r1;
                const float4 z = make_float4(0.f, 0.f, 0.f, 0.f);
                float4 a0, b0, a1, b1;
                if (gr0 < 500) {
                    const float4* g0 =
                        reinterpret_cast<const float4*>(centers + (size_t)gr0 * 65536 + k0);
                    a0 = g0[lid]; b0 = g0[lid + 32];
                } else { a0 = z; b0 = z; }
                if (gr1 < 500) {
                    const float4* g1 =
                        reinterpret_cast<const float4*>(centers + (size_t)gr1 * 65536 + k0);
                    a1 = g1[lid]; b1 = g1[lid + 32];
                } else { a1 = z; b1 = z; }
                *reinterpret_cast<uint2*>(tile + roff(r0, kA)) =
                    make_uint2(pack_bf16x2(a0.x, a0.y), pack_bf16x2(a0.z, a0.w));
                *reinterpret_cast<uint2*>(tile + roff(r0, kB)) =
                    make_uint2(pack_bf16x2(b0.x, b0.y), pack_bf16x2(b0.z, b0.w));
                *reinterpret_cast<uint2*>(tile + roff(r1, kA)) =
                    make_uint2(pack_bf16x2(a1.x, a1.y), pack_bf16x2(a1.z, a1.w));
                *reinterpret_cast<uint2*>(tile + roff(r1, kB)) =
                    make_uint2(pack_bf16x2(b1.x, b1.y), pack_bf16x2(b1.z, b1.w));
                float s0 = warp_sum(dot4(a0) + dot4(b0));
                float s1 = warp_sum(dot4(a1) + dot4(b1));
                if (lid == 0) {
                    if (gr0 < 500) g_csq_p[(size_t)gr0 * S_SPLIT + s] = s0;
                    if (gr1 < 500) g_csq_p[(size_t)gr1 * S_SPLIT + s] = s1;
                }
            }
        }
        __syncthreads();

        // ---- MMA: 32x16 warp tile over KC=256 ----
        float acc[2][2][4];
        #pragma unroll
        for (int mi = 0; mi < 2; mi++)
            #pragma unroll
            for (int g = 0; g < 2; g++)
                #pragma unroll
                for (int i = 0; i < 4; i++) acc[mi][g][i] = 0.f;

        #pragma unroll 8
        for (int kk = 0; kk < KC; kk += 16) {
            uint32_t af0[4], af1[4], bf[4];
            ldsm_x4(af0, cb + roff(mr + a_row,      kk + a_kd));
            ldsm_x4(af1, cb + roff(mr + 16 + a_row, kk + a_kd));
            ldsm_x4(bf,  xb + roff(b_row,           kk + b_kd));
            mma_bf16(acc[0][0], af0, bf);
            mma_bf16(acc[0][1], af0, bf + 2);
            mma_bf16(acc[1][0], af1, bf);
            mma_bf16(acc[1][1], af1, bf + 2);
        }

        // ---- store f16 partials ----
        {
            const int r0 = mh * 256 + sb * 64 + mr + (lid >> 2);
            const int c0 = nbase + (lid & 3) * 2;
            #pragma unroll
            for (int mi = 0; mi < 2; mi++) {
                #pragma unroll
                for (int g = 0; g < 2; g++) {
                    const int col = c0 + 8 * g;
                    __half* b0 = g_parth + (((size_t)(r0 + 16 * mi)     * S_SPLIT + s) << 6) + col;
                    __half* b1 = g_parth + (((size_t)(r0 + 16 * mi + 8) * S_SPLIT + s) << 6) + col;
                    *reinterpret_cast<__half2*>(b0) = __floats2half2_rn(acc[mi][g][0], acc[mi][g][1]);
                    *reinterpret_cast<__half2*>(b1) = __floats2half2_rn(acc[mi][g][2], acc[mi][g][3]);
                }
            }
        }
    }
}

// ============================================================================
// Kernel 2: reduce partials over S + finalize norms -> rbf[b][c]
// ============================================================================
__global__ void __launch_bounds__(512)
svm_rbf_kernel() {
    __shared__ float red [16][NB];
    __shared__ float redx[4][NB];
    __shared__ float s_csq;
    const int c   = blockIdx.x;          // 0..499
    const int tid = threadIdx.x;         // 512
    const int sp   = tid >> 5;           // 0..15 (16 s-values each)
    const int lane = tid & 31;

    // cross partials: coalesced half2 stream
    {
        const __half2* p =
            reinterpret_cast<const __half2*>(g_parth + ((size_t)c * S_SPLIT + sp * 16) * NB) + lane;
        float2 a = make_float2(0.f, 0.f);
        #pragma unroll
        for (int i = 0; i < 16; i++) {
            float2 f = __half22float2(p[(size_t)i * 32]);
            a.x += f.x; a.y += f.y;
        }
        red[sp][2 * lane]     = a.x;
        red[sp][2 * lane + 1] = a.y;
    }
    // xsq: 4 threads per batch row
    if (tid < 256) {
        const int b = tid >> 2, q = tid & 3;
        const float4* xp = reinterpret_cast<const float4*>(g_xsq_p + (size_t)b * S_SPLIT + q * 64);
        float v = 0.f;
        #pragma unroll
        for (int i = 0; i < 16; i++) {
            float4 t = xp[i];
            v += t.x + t.y + t.z + t.w;
        }
        redx[q][b] = v;
    }
    // csq: warp 0
    if (tid < 32) {
        const float4* cp = reinterpret_cast<const float4*>(g_csq_p + (size_t)c * S_SPLIT);
        float4 t0 = cp[tid], t1 = cp[tid + 32];
        float v = t0.x + t0.y + t0.z + t0.w + t1.x + t1.y + t1.z + t1.w;
        #pragma unroll
        for (int d = 16; d > 0; d >>= 1) v += __shfl_xor_sync(0xffffffffu, v, d);
        if (tid == 0) s_csq = v;
    }
    __syncthreads();
    if (tid < NB) {
        float cross = 0.f, xs = 0.f;
        #pragma unroll
        for (int i = 0; i < 16; i++) cross += red[i][tid];
        #pragma unroll
        for (int i = 0; i < 4; i++) xs += redx[i][tid];
        float dist = xs - 2.0f * cross + s_csq;
        g_rbf[(size_t)tid * NCPAD + c] = expf(-GAMMA_F * dist);   // [b][c]
    }
}

// ============================================================================
// Kernel 3: out[b][i] = sum_c rbf[b][c] * fc_w[i][c] + fc_b[i]
// ============================================================================
__global__ void svm_fc_kernel(const float* __restrict__ fc_w,
                              const float* __restrict__ fc_b,
                              float* __restrict__ out) {
    const int b   = blockIdx.x;          // 0..63
    const int i   = threadIdx.x >> 5;    // 0..7 output feature
    const int lid = threadIdx.x & 31;
    const float* rr = g_rbf + (size_t)b * NCPAD;
    float acc = 0.f;
    #pragma unroll 4
    for (int c = lid; c < 500; c += 32)
        acc += rr[c] * fc_w[i * 500 + c];
    #pragma unroll
    for (int d = 16; d > 0; d >>= 1) acc += __shfl_xor_sync(0xffffffffu, acc, d);
    if (lid == 0) out[b * 8 + i] = acc + fc_b[i];
}

// ============================================================================
extern "C" void kernel_launch(void* const* d_in, const int* in_sizes, int n_in,
                              void* d_out, int out_size) {
    const float* x       = (const float*)d_in[0];
    const float* centers = (const float*)d_in[1];
    const float* fc_w    = (const float*)d_in[2];
    const float* fc_b    = (const float*)d_in[3];
    float* out = (float*)d_out;

    cudaFuncSetAttribute(svm_main_kernel, cudaFuncAttributeMaxDynamicSharedMemorySize, SMEM_TOTAL);

    svm_main_kernel<<<2 * S_SPLIT, 256, SMEM_TOTAL>>>(x, centers);
    svm_rbf_kernel<<<500, 512>>>();
    svm_fc_kernel<<<NB, 256>>>(fc_w, fc_b, out);
}

// round 10
// speedup vs baseline: 1.7698x; 1.0977x over previous
#include <cuda_runtime.h>
#include <cuda_bf16.h>
#include <cuda_fp16.h>
#include <cstdint>

// ============================================================================
// out[64,8] = exp(-1e-4 * ||x_b - c_j||^2) @ fc_w.T + fc_b
//   x: [64, 65536] f32, centers: [500, 65536] f32
// K1: split-K x split-M, grid 512, 256 thr, 48KB smem, occ 4 -> SINGLE WAVE.
//     Per CTA: convert x chunk (32KB bf16, coalesced), then 8 sub-blocks of
//     32 center rows (16KB tile): convert -> k-split MMA (warps 0-3: k0-127,
//     warps 4-7: k128-255, each m32n16) -> smem acc exchange -> f16 partials.
// K2: reduce partials over S + norms -> rbf[b][c].
// K3: fc head, grid 512 (b x i) for single-wave latency.
// Base sm_100 only (harness compiles compute_100: no tcgen05).
// ============================================================================

#define GAMMA_F 1e-4f

static constexpr int S_SPLIT = 256;   // K chunks
static constexpr int KC      = 256;   // K per chunk
static constexpr int NB      = 64;    // batch
static constexpr int NCPAD   = 512;
static constexpr int NSB     = 8;     // 32-row center sub-blocks per CTA

// -------- scratch --------
__device__ __half g_parth[(size_t)NCPAD * S_SPLIT * NB];  // [c][s][b] 16 MB f16
__device__ float  g_csq_p[(size_t)NCPAD * S_SPLIT];
__device__ float  g_xsq_p[(size_t)NB    * S_SPLIT];       // [b][s]
__device__ float  g_rbf  [(size_t)NB * NCPAD];            // [b][c]

// -------- helpers --------
__device__ __forceinline__ uint32_t smem_u32(const void* p) {
    uint32_t a;
    asm("{ .reg .u64 t; cvta.to.shared.u64 t, %1; cvt.u32.u64 %0, t; }" : "=r"(a) : "l"(p));
    return a;
}
// 64-row tile (x): atoms 8 rows x 64 bf16; 8 atom-rows per 64-k block
__device__ __forceinline__ uint32_t roff64(int row, int k) {
    uint32_t r7 = (uint32_t)(row & 7);
    return (((uint32_t)(k >> 6) * 8u + (uint32_t)(row >> 3)) << 10)
         + r7 * 128u + (((uint32_t)(k & 63) * 2u) ^ (r7 << 4));
}
// 32-row tile (c): 4 atom-rows per 64-k block
__device__ __forceinline__ uint32_t roff32(int row, int k) {
    uint32_t r7 = (uint32_t)(row & 7);
    return (((uint32_t)(k >> 6) * 4u + (uint32_t)(row >> 3)) << 10)
         + r7 * 128u + (((uint32_t)(k & 63) * 2u) ^ (r7 << 4));
}
__device__ __forceinline__ uint32_t pack_bf16x2(float a, float b) {
    __nv_bfloat162 t = __floats2bfloat162_rn(a, b);
    return *reinterpret_cast<uint32_t*>(&t);
}
__device__ __forceinline__ void ldsm_x4(uint32_t* r, uint32_t addr) {
    asm volatile("ldmatrix.sync.aligned.m8n8.x4.shared.b16 {%0,%1,%2,%3}, [%4];"
                 : "=r"(r[0]), "=r"(r[1]), "=r"(r[2]), "=r"(r[3]) : "r"(addr));
}
__device__ __forceinline__ void mma_bf16(float* d, const uint32_t* a, const uint32_t* b) {
    asm volatile("mma.sync.aligned.m16n8k16.row.col.f32.bf16.bf16.f32 "
                 "{%0,%1,%2,%3}, {%4,%5,%6,%7}, {%8,%9}, {%0,%1,%2,%3};"
                 : "+f"(d[0]), "+f"(d[1]), "+f"(d[2]), "+f"(d[3])
                 : "r"(a[0]), "r"(a[1]), "r"(a[2]), "r"(a[3]), "r"(b[0]), "r"(b[1]));
}
__device__ __forceinline__ float dot4(float4 v) {
    return v.x * v.x + v.y * v.y + v.z * v.z + v.w * v.w;
}
__device__ __forceinline__ float warp_sum(float v) {
    #pragma unroll
    for (int d = 16; d > 0; d >>= 1) v += __shfl_xor_sync(0xffffffffu, v, d);
    return v;
}

// -------- SMEM: x 32KB | c 16KB (MMA-idle: acc-exchange scratch 8KB) --------
static constexpr int SMEM_X     = 0;
static constexpr int SMEM_C     = 32768;
static constexpr int SMEM_TOTAL = 49152;

// ============================================================================
// Kernel 1
// ============================================================================
__global__ void __launch_bounds__(256, 4)
svm_main_kernel(const float* __restrict__ x, const float* __restrict__ centers) {
    extern __shared__ char smem[];
    const uint32_t smem_base = smem_u32(smem);
    const int tid = threadIdx.x;
    const int wid = tid >> 5;
    const int lid = tid & 31;
    const int s   = blockIdx.x >> 1;       // k-chunk
    const int mh  = blockIdx.x & 1;        // m-half (center rows mh*256..)
    const size_t k0 = (size_t)s * KC;

    const int kA = 4 * lid, kB = 128 + 4 * lid;   // lane k coords within a row

    // ---- prologue: convert x chunk; warp w -> rows 8w..8w+7, coalesced ----
    {
        char* tile = smem + SMEM_X;
        #pragma unroll
        for (int q = 0; q < 8; q += 2) {
            const int r0 = wid * 8 + q, r1 = r0 + 1;
            const float4* g0 = reinterpret_cast<const float4*>(x + (size_t)r0 * 65536 + k0);
            const float4* g1 = reinterpret_cast<const float4*>(x + (size_t)r1 * 65536 + k0);
            float4 a0 = g0[lid], b0 = g0[lid + 32];
            float4 a1 = g1[lid], b1 = g1[lid + 32];
            *reinterpret_cast<uint2*>(tile + roff64(r0, kA)) =
                make_uint2(pack_bf16x2(a0.x, a0.y), pack_bf16x2(a0.z, a0.w));
            *reinterpret_cast<uint2*>(tile + roff64(r0, kB)) =
                make_uint2(pack_bf16x2(b0.x, b0.y), pack_bf16x2(b0.z, b0.w));
            *reinterpret_cast<uint2*>(tile + roff64(r1, kA)) =
                make_uint2(pack_bf16x2(a1.x, a1.y), pack_bf16x2(a1.z, a1.w));
            *reinterpret_cast<uint2*>(tile + roff64(r1, kB)) =
                make_uint2(pack_bf16x2(b1.x, b1.y), pack_bf16x2(b1.z, b1.w));
            float s0 = warp_sum(dot4(a0) + dot4(b0));
            float s1 = warp_sum(dot4(a1) + dot4(b1));
            if (mh == 0 && lid == 0) {
                g_xsq_p[(size_t)r0 * S_SPLIT + s] = s0;
                g_xsq_p[(size_t)r1 * S_SPLIT + s] = s1;
            }
        }
    }

    // ---- warp roles: khalf = k range, j4 = n-column group ----
    const int khalf = wid >> 2;            // 0: k 0..127, 1: k 128..255
    const int j4    = wid & 3;
    const int nbase = j4 * 16;
    const int kbase = khalf * 128;
    const int sel = lid >> 3;
    const int l7  = lid & 7;
    const int a_row = l7 + (sel & 1) * 8;
    const int a_kd  = (sel >> 1) * 8;
    const int b_row = nbase + l7 + (sel >> 1) * 8;
    const int b_kd  = (sel & 1) * 8;
    const uint32_t xb = smem_base + SMEM_X;
    const uint32_t cb = smem_base + SMEM_C;
    float* scratch = reinterpret_cast<float*>(smem + SMEM_C);   // overlaid

    for (int sb = 0; sb < NSB; sb++) {
        __syncthreads();   // prev MMA + scratch reads done -> c region free

        // ---- convert center sub-block (32 rows; warp w -> rows 4w..4w+3) ----
        {
            char* tile = smem + SMEM_C;
            const int gbase = mh * 256 + sb * 32;
            #pragma unroll
            for (int q = 0; q < 4; q += 2) {
                const int r0 = wid * 4 + q, r1 = r0 + 1;
                const int gr0 = gbase + r0, gr1 = gbase + r1;
                const float4 z = make_float4(0.f, 0.f, 0.f, 0.f);
                float4 a0, b0, a1, b1;
                if (gr0 < 500) {
                    const float4* g0 =
                        reinterpret_cast<const float4*>(centers + (size_t)gr0 * 65536 + k0);
                    a0 = g0[lid]; b0 = g0[lid + 32];
                } else { a0 = z; b0 = z; }
                if (gr1 < 500) {
                    const float4* g1 =
                        reinterpret_cast<const float4*>(centers + (size_t)gr1 * 65536 + k0);
                    a1 = g1[lid]; b1 = g1[lid + 32];
                } else { a1 = z; b1 = z; }
                *reinterpret_cast<uint2*>(tile + roff32(r0, kA)) =
                    make_uint2(pack_bf16x2(a0.x, a0.y), pack_bf16x2(a0.z, a0.w));
                *reinterpret_cast<uint2*>(tile + roff32(r0, kB)) =
                    make_uint2(pack_bf16x2(b0.x, b0.y), pack_bf16x2(b0.z, b0.w));
                *reinterpret_cast<uint2*>(tile + roff32(r1, kA)) =
                    make_uint2(pack_bf16x2(a1.x, a1.y), pack_bf16x2(a1.z, a1.w));
                *reinterpret_cast<uint2*>(tile + roff32(r1, kB)) =
                    make_uint2(pack_bf16x2(b1.x, b1.y), pack_bf16x2(b1.z, b1.w));
                float s0 = warp_sum(dot4(a0) + dot4(b0));
                float s1 = warp_sum(dot4(a1) + dot4(b1));
                if (lid == 0) {
                    if (gr0 < 500) g_csq_p[(size_t)gr0 * S_SPLIT + s] = s0;
                    if (gr1 < 500) g_csq_p[(size_t)gr1 * S_SPLIT + s] = s1;
                }
            }
        }
        __syncthreads();

        // ---- MMA: warp tile m32 x n16 over its 128-k half ----
        float acc[16];                       // [mi(2)][ni(2)][4]
        #pragma unroll
        for (int i = 0; i < 16; i++) acc[i] = 0.f;

        #pragma unroll 8
        for (int kk = 0; kk < 128; kk += 16) {
            uint32_t af0[4], af1[4], bf[4];
            ldsm_x4(af0, cb + roff32(a_row,      kbase + kk + a_kd));
            ldsm_x4(af1, cb + roff32(16 + a_row, kbase + kk + a_kd));
            ldsm_x4(bf,  xb + roff64(b_row,      kbase + kk + b_kd));
            mma_bf16(acc + 0,  af0, bf);       // mi0 ni0
            mma_bf16(acc + 4,  af0, bf + 2);   // mi0 ni1
            mma_bf16(acc + 8,  af1, bf);       // mi1 ni0
            mma_bf16(acc + 12, af1, bf + 2);   // mi1 ni1
        }
        __syncthreads();   // all ldsm reads of c tile done -> scratch writable

        // ---- k-half exchange: warps 4-7 publish, warps 0-3 combine+store ----
        if (khalf == 1) {
            float4* dst = reinterpret_cast<float4*>(scratch) + (j4 * 32 + lid) * 4;
            dst[0] = make_float4(acc[0],  acc[1],  acc[2],  acc[3]);
            dst[1] = make_float4(acc[4],  acc[5],  acc[6],  acc[7]);
            dst[2] = make_float4(acc[8],  acc[9],  acc[10], acc[11]);
            dst[3] = make_float4(acc[12], acc[13], acc[14], acc[15]);
        }
        __syncthreads();
        if (khalf == 0) {
            const float4* src = reinterpret_cast<const float4*>(scratch) + (j4 * 32 + lid) * 4;
            #pragma unroll
            for (int i4 = 0; i4 < 4; i4++) {
                float4 v = src[i4];
                acc[4 * i4 + 0] += v.x; acc[4 * i4 + 1] += v.y;
                acc[4 * i4 + 2] += v.z; acc[4 * i4 + 3] += v.w;
            }
            const int r0 = mh * 256 + sb * 32 + (lid >> 2);
            const int c0 = nbase + (lid & 3) * 2;
            #pragma unroll
            for (int mi = 0; mi < 2; mi++) {
                #pragma unroll
                for (int ni = 0; ni < 2; ni++) {
                    const int col = c0 + 8 * ni;
                    const float* a4 = acc + mi * 8 + ni * 4;
                    __half* b0 = g_parth + (((size_t)(r0 + 16 * mi)     * S_SPLIT + s) << 6) + col;
                    __half* b1 = g_parth + (((size_t)(r0 + 16 * mi + 8) * S_SPLIT + s) << 6) + col;
                    *reinterpret_cast<__half2*>(b0) = __floats2half2_rn(a4[0], a4[1]);
                    *reinterpret_cast<__half2*>(b1) = __floats2half2_rn(a4[2], a4[3]);
                }
            }
        }
    }
}

// ============================================================================
// Kernel 2: reduce partials over S + finalize norms -> rbf[b][c]
// ============================================================================
__global__ void __launch_bounds__(512)
svm_rbf_kernel() {
    __shared__ float red [16][NB];
    __shared__ float redx[4][NB];
    __shared__ float s_csq;
    const int c   = blockIdx.x;          // 0..499
    const int tid = threadIdx.x;         // 512
    const int sp   = tid >> 5;           // 0..15 (16 s-values each)
    const int lane = tid & 31;

    {
        const __half2* p =
            reinterpret_cast<const __half2*>(g_parth + ((size_t)c * S_SPLIT + sp * 16) * NB) + lane;
        float2 a = make_float2(0.f, 0.f);
        #pragma unroll
        for (int i = 0; i < 16; i++) {
            float2 f = __half22float2(p[(size_t)i * 32]);
            a.x += f.x; a.y += f.y;
        }
        red[sp][2 * lane]     = a.x;
        red[sp][2 * lane + 1] = a.y;
    }
    if (tid < 256) {
        const int b = tid >> 2, q = tid & 3;
        const float4* xp = reinterpret_cast<const float4*>(g_xsq_p + (size_t)b * S_SPLIT + q * 64);
        float v = 0.f;
        #pragma unroll
        for (int i = 0; i < 16; i++) {
            float4 t = xp[i];
            v += t.x + t.y + t.z + t.w;
        }
        redx[q][b] = v;
    }
    if (tid < 32) {
        const float4* cp = reinterpret_cast<const float4*>(g_csq_p + (size_t)c * S_SPLIT);
        float4 t0 = cp[tid], t1 = cp[tid + 32];
        float v = t0.x + t0.y + t0.z + t0.w + t1.x + t1.y + t1.z + t1.w;
        #pragma unroll
        for (int d = 16; d > 0; d >>= 1) v += __shfl_xor_sync(0xffffffffu, v, d);
        if (tid == 0) s_csq = v;
    }
    __syncthreads();
    if (tid < NB) {
        float cross = 0.f, xs = 0.f;
        #pragma unroll
        for (int i = 0; i < 16; i++) cross += red[i][tid];
        #pragma unroll
        for (int i = 0; i < 4; i++) xs += redx[i][tid];
        float dist = xs - 2.0f * cross + s_csq;
        g_rbf[(size_t)tid * NCPAD + c] = expf(-GAMMA_F * dist);   // [b][c]
    }
}

// ============================================================================
// Kernel 3: out[b][i] = sum_c rbf[b][c] * fc_w[i][c] + fc_b[i]
//   grid 512 = (b, i), block 128 — single wave, short serial chains
// ============================================================================
__global__ void __launch_bounds__(128)
svm_fc_kernel(const float* __restrict__ fc_w,
              const float* __restrict__ fc_b,
              float* __restrict__ out) {
    __shared__ float w4[4];
    const int b = blockIdx.x >> 3;
    const int i = blockIdx.x & 7;
    const int t = threadIdx.x;
    const float* rr = g_rbf + (size_t)b * NCPAD;
    const float* ww = fc_w + i * 500;
    float acc = 0.f;
    #pragma unroll
    for (int q = 0; q < 4; q++) {
        int c = t + q * 128;
        if (c < 500) acc += rr[c] * ww[c];
    }
    acc = warp_sum(acc);
    if ((t & 31) == 0) w4[t >> 5] = acc;
    __syncthreads();
    if (t == 0) out[b * 8 + i] = w4[0] + w4[1] + w4[2] + w4[3] + fc_b[i];
}

// ============================================================================
extern "C" void kernel_launch(void* const* d_in, const int* in_sizes, int n_in,
                              void* d_out, int out_size) {
    const float* x       = (const float*)d_in[0];
    const float* centers = (const float*)d_in[1];
    const float* fc_w    = (const float*)d_in[2];
    const float* fc_b    = (const float*)d_in[3];
    float* out = (float*)d_out;

    cudaFuncSetAttribute(svm_main_kernel, cudaFuncAttributeMaxDynamicSharedMemorySize, SMEM_TOTAL);

    svm_main_kernel<<<2 * S_SPLIT, 256, SMEM_TOTAL>>>(x, centers);
    svm_rbf_kernel<<<500, 512>>>();
    svm_fc_kernel<<<512, 128>>>(fc_w, fc_b, out);
}